// round 13
// baseline (speedup 1.0000x reference)
#include <cuda_runtime.h>
#include <cuda_bf16.h>
#include <cstdint>

// FeatureBank, single-kernel: out = memory, except rows y[i] get
// normalize(0.5*memory[y[i]] + 0.5*x[i])
//
// Inputs: x [4096,128] f32, y [4096] int32, memory [500000,128] f32
// Output: new_memory [500000,128] f32
//
// One graph node. Block 0 scatters y into g_row_map and releases g_flag;
// all blocks issue their streaming loads first, then spin on the flag
// (volatile L2 read + nanosleep), then copy/update their 4 rows.
// State invariants restored in-kernel: dirty warps zero their map entry,
// the last block to finish resets flag + done-counter.

#define MOMENTUM 0.5f
#define DIM 128
#define BATCH 4096
#define N_ROWS 500000

#define THREADS 256
#define ROWS_PER_WARP 4
#define WARPS_PER_BLOCK (THREADS / 32)
// 500000 / 4 / 8 = 15625 blocks, exact
#define NBLOCKS (N_ROWS / ROWS_PER_WARP / WARPS_PER_BLOCK)

__device__ int g_row_map[N_ROWS];  // 2 MB, zero outside a call
__device__ int g_flag;             // 0 outside a call
__device__ int g_done;             // 0 outside a call

__device__ __forceinline__ void process_row(int row, int lane, float4 mv,
                                            const float* __restrict__ x,
                                            float* __restrict__ out,
                                            int m) {
    float4* dst = reinterpret_cast<float4*>(out + (size_t)row * DIM);
    if (m == 0) {
        __stcs(dst + lane, mv);
    } else {
        const float4* xr = reinterpret_cast<const float4*>(x + (size_t)(m - 1) * DIM);
        float4 xv = xr[lane];

        float4 w;
        w.x = mv.x * MOMENTUM + xv.x * (1.0f - MOMENTUM);
        w.y = mv.y * MOMENTUM + xv.y * (1.0f - MOMENTUM);
        w.z = mv.z * MOMENTUM + xv.z * (1.0f - MOMENTUM);
        w.w = mv.w * MOMENTUM + xv.w * (1.0f - MOMENTUM);

        float ss = w.x * w.x + w.y * w.y + w.z * w.z + w.w * w.w;
        #pragma unroll
        for (int off = 16; off > 0; off >>= 1)
            ss += __shfl_xor_sync(0xFFFFFFFFu, ss, off);

        float inv = rsqrtf(ss);

        float4 o;
        o.x = w.x * inv;
        o.y = w.y * inv;
        o.z = w.z * inv;
        o.w = w.w * inv;
        dst[lane] = o;

        if (lane == 0) g_row_map[row] = 0;  // restore map invariant
    }
}

__global__ void __launch_bounds__(THREADS) featurebank_fused_kernel(
        const float* __restrict__ x,
        const int* __restrict__ y,
        const float* __restrict__ memory,
        float* __restrict__ out) {
    int tid = threadIdx.x;
    int lane = tid & 31;
    int warp_global = (blockIdx.x * THREADS + tid) >> 5;
    int r0 = warp_global * ROWS_PER_WARP;

    // Block 0: scatter dirty-row map, then release the flag.
    if (blockIdx.x == 0) {
        #pragma unroll 4
        for (int i = tid; i < BATCH; i += THREADS)
            g_row_map[y[i]] = i + 1;
        __threadfence();
        __syncthreads();
        if (tid == 0) atomicExch(&g_flag, 1);
    }

    // Issue streaming loads for my 4 contiguous rows (2 KB per warp) before
    // waiting — hides the scatter under DRAM latency.
    const float4* src = reinterpret_cast<const float4*>(memory + (size_t)r0 * DIM);
    float4 mv0 = __ldcs(src + 0 * 32 + lane);
    float4 mv1 = __ldcs(src + 1 * 32 + lane);
    float4 mv2 = __ldcs(src + 2 * 32 + lane);
    float4 mv3 = __ldcs(src + 3 * 32 + lane);

    // Wait for the scatter to be visible (block 0 already knows it's done).
    if (blockIdx.x != 0) {
        if (tid == 0) {
            while (*((volatile int*)&g_flag) == 0) __nanosleep(64);
        }
        __syncthreads();
    }

    // Read dirty markers for my 4 rows (L2-fresh).
    int mm = 0;
    if (lane < ROWS_PER_WARP) mm = __ldcg(&g_row_map[r0 + lane]);
    int m0 = __shfl_sync(0xFFFFFFFFu, mm, 0);
    int m1 = __shfl_sync(0xFFFFFFFFu, mm, 1);
    int m2 = __shfl_sync(0xFFFFFFFFu, mm, 2);
    int m3 = __shfl_sync(0xFFFFFFFFu, mm, 3);

    process_row(r0 + 0, lane, mv0, x, out, m0);
    process_row(r0 + 1, lane, mv1, x, out, m1);
    process_row(r0 + 2, lane, mv2, x, out, m2);
    process_row(r0 + 3, lane, mv3, x, out, m3);

    // Last block to finish resets the flag/counter for the next graph replay.
    __syncthreads();
    if (tid == 0) {
        if (atomicAdd(&g_done, 1) == NBLOCKS - 1) {
            g_done = 0;
            g_flag = 0;
        }
    }
}

extern "C" void kernel_launch(void* const* d_in, const int* in_sizes, int n_in,
                              void* d_out, int out_size) {
    const float* x      = (const float*)d_in[0];
    const int*   y      = (const int*)d_in[1];
    const float* memory = (const float*)d_in[2];
    float*       out    = (float*)d_out;

    featurebank_fused_kernel<<<NBLOCKS, THREADS>>>(x, y, memory, out);
}

// round 15
// speedup vs baseline: 1.0264x; 1.0264x over previous
#include <cuda_runtime.h>
#include <cuda_bf16.h>
#include <cstdint>

// FeatureBank, single-kernel: out = memory, except rows y[i] get
// normalize(0.5*memory[y[i]] + 0.5*x[i])
//
// Inputs: x [4096,128] f32, y [4096] int32, memory [500000,128] f32
// Output: new_memory [500000,128] f32
//
// One graph node. The first SCATTER_BLOCKS blocks each scatter a 128-entry
// slice of y into g_row_map, fence, and bump g_flag; every block issues its
// streaming row loads first, then spins until g_flag == SCATTER_BLOCKS, then
// copies/updates its 4 rows. Dirty warps self-reset their map entry; the last
// block to finish resets flag + done-counter (all-zero invariant preserved
// across graph replays).

#define MOMENTUM 0.5f
#define DIM 128
#define BATCH 4096
#define N_ROWS 500000

#define THREADS 256
#define ROWS_PER_WARP 4
#define WARPS_PER_BLOCK (THREADS / 32)
#define NBLOCKS (N_ROWS / ROWS_PER_WARP / WARPS_PER_BLOCK)   // 15625

#define SCATTER_BLOCKS 32
#define Y_PER_SCATTER (BATCH / SCATTER_BLOCKS)               // 128

__device__ int g_row_map[N_ROWS];  // 2 MB, zero outside a call
__device__ int g_flag;             // 0 outside a call
__device__ int g_done;             // 0 outside a call

__device__ __forceinline__ void process_row(int row, int lane, float4 mv,
                                            const float* __restrict__ x,
                                            float* __restrict__ out,
                                            int m) {
    float4* dst = reinterpret_cast<float4*>(out + (size_t)row * DIM);
    if (m == 0) {
        __stcs(dst + lane, mv);
    } else {
        const float4* xr = reinterpret_cast<const float4*>(x + (size_t)(m - 1) * DIM);
        float4 xv = xr[lane];

        float4 w;
        w.x = mv.x * MOMENTUM + xv.x * (1.0f - MOMENTUM);
        w.y = mv.y * MOMENTUM + xv.y * (1.0f - MOMENTUM);
        w.z = mv.z * MOMENTUM + xv.z * (1.0f - MOMENTUM);
        w.w = mv.w * MOMENTUM + xv.w * (1.0f - MOMENTUM);

        float ss = w.x * w.x + w.y * w.y + w.z * w.z + w.w * w.w;
        #pragma unroll
        for (int off = 16; off > 0; off >>= 1)
            ss += __shfl_xor_sync(0xFFFFFFFFu, ss, off);

        float inv = rsqrtf(ss);

        float4 o;
        o.x = w.x * inv;
        o.y = w.y * inv;
        o.z = w.z * inv;
        o.w = w.w * inv;
        dst[lane] = o;

        if (lane == 0) g_row_map[row] = 0;  // restore map invariant
    }
}

__global__ void __launch_bounds__(THREADS) featurebank_fused_kernel(
        const float* __restrict__ x,
        const int* __restrict__ y,
        const float* __restrict__ memory,
        float* __restrict__ out) {
    int tid = threadIdx.x;
    int lane = tid & 31;
    int warp_global = (blockIdx.x * THREADS + tid) >> 5;
    int r0 = warp_global * ROWS_PER_WARP;

    // Parallel scatter: blocks 0..31 each mark 128 dirty rows, then bump flag.
    if (blockIdx.x < SCATTER_BLOCKS) {
        if (tid < Y_PER_SCATTER) {
            int i = blockIdx.x * Y_PER_SCATTER + tid;
            g_row_map[y[i]] = i + 1;
        }
        __threadfence();
        __syncthreads();
        if (tid == 0) atomicAdd(&g_flag, 1);
    }

    // Issue streaming loads for my 4 contiguous rows (2 KB/warp) before the
    // wait — the scatter hides under DRAM latency.
    const float4* src = reinterpret_cast<const float4*>(memory + (size_t)r0 * DIM);
    float4 mv0 = __ldcs(src + 0 * 32 + lane);
    float4 mv1 = __ldcs(src + 1 * 32 + lane);
    float4 mv2 = __ldcs(src + 2 * 32 + lane);
    float4 mv3 = __ldcs(src + 3 * 32 + lane);

    // Wait until all 32 scatter slices are published.
    if (tid == 0) {
        while (*((volatile int*)&g_flag) != SCATTER_BLOCKS) __nanosleep(32);
    }
    __syncthreads();

    // Read dirty markers for my 4 rows (L2-fresh).
    int mm = 0;
    if (lane < ROWS_PER_WARP) mm = __ldcg(&g_row_map[r0 + lane]);
    int m0 = __shfl_sync(0xFFFFFFFFu, mm, 0);
    int m1 = __shfl_sync(0xFFFFFFFFu, mm, 1);
    int m2 = __shfl_sync(0xFFFFFFFFu, mm, 2);
    int m3 = __shfl_sync(0xFFFFFFFFu, mm, 3);

    process_row(r0 + 0, lane, mv0, x, out, m0);
    process_row(r0 + 1, lane, mv1, x, out, m1);
    process_row(r0 + 2, lane, mv2, x, out, m2);
    process_row(r0 + 3, lane, mv3, x, out, m3);

    // Last block to finish resets flag/counter for the next graph replay.
    __syncthreads();
    if (tid == 0) {
        if (atomicAdd(&g_done, 1) == NBLOCKS - 1) {
            g_done = 0;
            g_flag = 0;
        }
    }
}

extern "C" void kernel_launch(void* const* d_in, const int* in_sizes, int n_in,
                              void* d_out, int out_size) {
    const float* x      = (const float*)d_in[0];
    const int*   y      = (const int*)d_in[1];
    const float* memory = (const float*)d_in[2];
    float*       out    = (float*)d_out;

    featurebank_fused_kernel<<<NBLOCKS, THREADS>>>(x, y, memory, out);
}

// round 16
// speedup vs baseline: 1.0322x; 1.0056x over previous
#include <cuda_runtime.h>
#include <cuda_bf16.h>
#include <cstdint>

// FeatureBank, stateless single-kernel:
//   out = memory, except rows y[i] get normalize(0.5*memory[y[i]] + 0.5*x[i])
//
// Inputs: x [4096,128] f32, y [4096] int32, memory [500000,128] f32
// Output: new_memory [500000,128] f32
//
// No global sync, no device state: each block owns 32 contiguous rows and
// scans the whole y vector (16 KB, L1-resident per SM after the first block)
// to build a local dirty table in smem. Expected dirty rows per block: 0.26,
// so the hot path is a pure streaming copy.

#define MOMENTUM 0.5f
#define DIM 128
#define BATCH 4096
#define N_ROWS 500000

#define THREADS 256
#define ROWS_PER_WARP 4
#define WARPS_PER_BLOCK (THREADS / 32)
#define ROWS_PER_BLOCK (ROWS_PER_WARP * WARPS_PER_BLOCK)     // 32
#define NBLOCKS (N_ROWS / ROWS_PER_BLOCK)                    // 15625, exact
#define Y_INT4 (BATCH / 4)                                   // 1024
#define Y_ITERS (Y_INT4 / THREADS)                           // 4

__device__ __forceinline__ void process_row(int row, int lane, float4 mv,
                                            const float* __restrict__ x,
                                            float* __restrict__ out,
                                            int m) {
    float4* dst = reinterpret_cast<float4*>(out + (size_t)row * DIM);
    if (m == 0) {
        __stcs(dst + lane, mv);
    } else {
        const float4* xr = reinterpret_cast<const float4*>(x + (size_t)(m - 1) * DIM);
        float4 xv = xr[lane];

        float4 w;
        w.x = mv.x * MOMENTUM + xv.x * (1.0f - MOMENTUM);
        w.y = mv.y * MOMENTUM + xv.y * (1.0f - MOMENTUM);
        w.z = mv.z * MOMENTUM + xv.z * (1.0f - MOMENTUM);
        w.w = mv.w * MOMENTUM + xv.w * (1.0f - MOMENTUM);

        float ss = w.x * w.x + w.y * w.y + w.z * w.z + w.w * w.w;
        #pragma unroll
        for (int off = 16; off > 0; off >>= 1)
            ss += __shfl_xor_sync(0xFFFFFFFFu, ss, off);

        float inv = rsqrtf(ss);

        float4 o;
        o.x = w.x * inv;
        o.y = w.y * inv;
        o.z = w.z * inv;
        o.w = w.w * inv;
        dst[lane] = o;
    }
}

__global__ void __launch_bounds__(THREADS) featurebank_fused_kernel(
        const float* __restrict__ x,
        const int* __restrict__ y,
        const float* __restrict__ memory,
        float* __restrict__ out) {
    __shared__ int dirty[ROWS_PER_BLOCK];   // dirty[r-base] = i+1, else 0

    int tid = threadIdx.x;
    int lane = tid & 31;
    int warp = tid >> 5;
    int base = blockIdx.x * ROWS_PER_BLOCK;

    if (tid < ROWS_PER_BLOCK) dirty[tid] = 0;
    __syncthreads();

    // Scan all of y (1024 int4, coalesced; L1-resident per SM after 1st block).
    const int4* y4 = reinterpret_cast<const int4*>(y);
    #pragma unroll
    for (int k = 0; k < Y_ITERS; k++) {
        int j = k * THREADS + tid;
        int4 v = __ldg(y4 + j);
        int i0 = 4 * j;
        unsigned u;
        u = (unsigned)(v.x - base); if (u < ROWS_PER_BLOCK) dirty[u] = i0 + 1;
        u = (unsigned)(v.y - base); if (u < ROWS_PER_BLOCK) dirty[u] = i0 + 2;
        u = (unsigned)(v.z - base); if (u < ROWS_PER_BLOCK) dirty[u] = i0 + 3;
        u = (unsigned)(v.w - base); if (u < ROWS_PER_BLOCK) dirty[u] = i0 + 4;
    }
    __syncthreads();

    // Each warp copies/updates its 4 contiguous rows (2-row unroll for MLP).
    int r0 = base + warp * ROWS_PER_WARP;
    const float4* src = reinterpret_cast<const float4*>(memory + (size_t)r0 * DIM);

    float4 mv0 = __ldcs(src + 0 * 32 + lane);
    float4 mv1 = __ldcs(src + 1 * 32 + lane);
    int m0 = dirty[r0 + 0 - base];
    int m1 = dirty[r0 + 1 - base];

    float4 mv2 = __ldcs(src + 2 * 32 + lane);
    float4 mv3 = __ldcs(src + 3 * 32 + lane);
    int m2 = dirty[r0 + 2 - base];
    int m3 = dirty[r0 + 3 - base];

    process_row(r0 + 0, lane, mv0, x, out, m0);
    process_row(r0 + 1, lane, mv1, x, out, m1);
    process_row(r0 + 2, lane, mv2, x, out, m2);
    process_row(r0 + 3, lane, mv3, x, out, m3);
}

extern "C" void kernel_launch(void* const* d_in, const int* in_sizes, int n_in,
                              void* d_out, int out_size) {
    const float* x      = (const float*)d_in[0];
    const int*   y      = (const int*)d_in[1];
    const float* memory = (const float*)d_in[2];
    float*       out    = (float*)d_out;

    featurebank_fused_kernel<<<NBLOCKS, THREADS>>>(x, y, memory, out);
}

// round 17
// speedup vs baseline: 1.0360x; 1.0036x over previous
#include <cuda_runtime.h>
#include <cuda_bf16.h>
#include <cstdint>

// FeatureBank, stateless single-kernel:
//   out = memory, except rows y[i] get normalize(0.5*memory[y[i]] + 0.5*x[i])
//
// Inputs: x [4096,128] f32, y [4096] int32, memory [500000,128] f32
// Output: new_memory [500000,128] f32
//
// Each block owns 32 contiguous rows. It ISSUES its streaming row loads first
// (LDG is non-blocking; barriers don't drain it), then scans the 16 KB y
// vector (L1-resident per SM after the first block) into a smem dirty table
// while those loads are in flight, then consumes the loads. Expected dirty
// rows per block: 4096*32/500000 = 0.26 -> hot path is a pure streaming copy.

#define MOMENTUM 0.5f
#define DIM 128
#define BATCH 4096
#define N_ROWS 500000

#define THREADS 256
#define ROWS_PER_WARP 4
#define WARPS_PER_BLOCK (THREADS / 32)
#define ROWS_PER_BLOCK (ROWS_PER_WARP * WARPS_PER_BLOCK)     // 32
#define NBLOCKS (N_ROWS / ROWS_PER_BLOCK)                    // 15625, exact
#define Y_INT4 (BATCH / 4)                                   // 1024
#define Y_ITERS (Y_INT4 / THREADS)                           // 4

__device__ __forceinline__ void process_row(int row, int lane, float4 mv,
                                            const float* __restrict__ x,
                                            float* __restrict__ out,
                                            int m) {
    float4* dst = reinterpret_cast<float4*>(out + (size_t)row * DIM);
    if (m == 0) {
        __stcs(dst + lane, mv);
    } else {
        const float4* xr = reinterpret_cast<const float4*>(x + (size_t)(m - 1) * DIM);
        float4 xv = xr[lane];

        float4 w;
        w.x = mv.x * MOMENTUM + xv.x * (1.0f - MOMENTUM);
        w.y = mv.y * MOMENTUM + xv.y * (1.0f - MOMENTUM);
        w.z = mv.z * MOMENTUM + xv.z * (1.0f - MOMENTUM);
        w.w = mv.w * MOMENTUM + xv.w * (1.0f - MOMENTUM);

        float ss = w.x * w.x + w.y * w.y + w.z * w.z + w.w * w.w;
        #pragma unroll
        for (int off = 16; off > 0; off >>= 1)
            ss += __shfl_xor_sync(0xFFFFFFFFu, ss, off);

        float inv = rsqrtf(ss);

        float4 o;
        o.x = w.x * inv;
        o.y = w.y * inv;
        o.z = w.z * inv;
        o.w = w.w * inv;
        dst[lane] = o;
    }
}

__global__ void __launch_bounds__(THREADS) featurebank_fused_kernel(
        const float* __restrict__ x,
        const int* __restrict__ y,
        const float* __restrict__ memory,
        float* __restrict__ out) {
    __shared__ int dirty[ROWS_PER_BLOCK];   // dirty[r-base] = i+1, else 0

    int tid = threadIdx.x;
    int lane = tid & 31;
    int warp = tid >> 5;
    int base = blockIdx.x * ROWS_PER_BLOCK;
    int r0 = base + warp * ROWS_PER_WARP;

    // ---- Issue the streaming DRAM loads FIRST (non-blocking). The scan below
    // executes entirely under their ~600-cycle latency.
    const float4* src = reinterpret_cast<const float4*>(memory + (size_t)r0 * DIM);
    float4 mv0 = __ldcs(src + 0 * 32 + lane);
    float4 mv1 = __ldcs(src + 1 * 32 + lane);
    float4 mv2 = __ldcs(src + 2 * 32 + lane);
    float4 mv3 = __ldcs(src + 3 * 32 + lane);

    // ---- Dirty-table build (smem), overlapped with the loads above.
    if (tid < ROWS_PER_BLOCK) dirty[tid] = 0;
    __syncthreads();

    const int4* y4 = reinterpret_cast<const int4*>(y);
    #pragma unroll
    for (int k = 0; k < Y_ITERS; k++) {
        int j = k * THREADS + tid;
        int4 v = __ldg(y4 + j);
        int i0 = 4 * j;
        unsigned u;
        u = (unsigned)(v.x - base); if (u < ROWS_PER_BLOCK) dirty[u] = i0 + 1;
        u = (unsigned)(v.y - base); if (u < ROWS_PER_BLOCK) dirty[u] = i0 + 2;
        u = (unsigned)(v.z - base); if (u < ROWS_PER_BLOCK) dirty[u] = i0 + 3;
        u = (unsigned)(v.w - base); if (u < ROWS_PER_BLOCK) dirty[u] = i0 + 4;
    }
    __syncthreads();

    int m0 = dirty[warp * ROWS_PER_WARP + 0];
    int m1 = dirty[warp * ROWS_PER_WARP + 1];
    int m2 = dirty[warp * ROWS_PER_WARP + 2];
    int m3 = dirty[warp * ROWS_PER_WARP + 3];

    // ---- Consume the loads (first use; stalls only on remaining latency).
    process_row(r0 + 0, lane, mv0, x, out, m0);
    process_row(r0 + 1, lane, mv1, x, out, m1);
    process_row(r0 + 2, lane, mv2, x, out, m2);
    process_row(r0 + 3, lane, mv3, x, out, m3);
}

extern "C" void kernel_launch(void* const* d_in, const int* in_sizes, int n_in,
                              void* d_out, int out_size) {
    const float* x      = (const float*)d_in[0];
    const int*   y      = (const int*)d_in[1];
    const float* memory = (const float*)d_in[2];
    float*       out    = (float*)d_out;

    featurebank_fused_kernel<<<NBLOCKS, THREADS>>>(x, y, memory, out);
}